// round 4
// baseline (speedup 1.0000x reference)
#include <cuda_runtime.h>

#define Nn 8
#define Cc 64
#define Hh 256
#define Ww 256
#define Pp 16          // cluster: 8 col-groups x 2 ch-groups
#define WC 32
#define FSTR 34
#define NT 128
#define HW (Hh*Ww)

// float-index offsets in smem
#define WS_F    0                      // weights: 6144 floats
#define FB_F(b) (6144 + (b)*2176)      // fn tile  [64 ch][34]
#define YB_F(b) (10496 + (b)*2176)     // y  tile  [34 col][64 ch]
#define ML_F(b) (14848 + (b)*1024)     // mail     [16 rank][64]
// byte offsets
#define BAR_B(b) (67584 + (b)*8)
#define SMEM_BYTES 67616

__device__ float g_stack[(size_t)Nn * Cc * Hh * Ww];

extern __shared__ float sm[];

__device__ __forceinline__ void csync() {
    asm volatile("barrier.cluster.arrive.aligned;" ::: "memory");
    asm volatile("barrier.cluster.wait.aligned;" ::: "memory");
}
__device__ __forceinline__ unsigned mapa_rank(unsigned laddr, unsigned rank) {
    unsigned ra;
    asm("mapa.shared::cluster.u32 %0, %1, %2;" : "=r"(ra) : "r"(laddr), "r"(rank));
    return ra;
}
__device__ __forceinline__ void mbar_init(unsigned a, unsigned cnt) {
    asm volatile("mbarrier.init.shared.b64 [%0], %1;" :: "r"(a), "r"(cnt) : "memory");
}
__device__ __forceinline__ void mbar_expect(unsigned a, unsigned bytes) {
    asm volatile("mbarrier.arrive.expect_tx.shared.b64 _, [%0], %1;"
                 :: "r"(a), "r"(bytes) : "memory");
}
__device__ __forceinline__ void mbar_wait(unsigned a, int phase) {
    asm volatile(
        "{\n\t.reg .pred P;\n"
        "LW_%=:\n\t"
        "mbarrier.try_wait.parity.acquire.cluster.shared::cta.b64 P, [%0], %1, 0x989680;\n\t"
        "@P bra LD_%=;\n\t"
        "bra LW_%=;\n"
        "LD_%=:\n\t}"
        :: "r"(a), "r"(phase) : "memory");
}
// data store with completion riding to the target CTA's mbarrier
__device__ __forceinline__ void st_async_b64(unsigned raddr, unsigned long long v, unsigned rbar) {
    asm volatile("st.async.shared::cluster.mbarrier::complete_tx::bytes.b64 [%0], %1, [%2];"
                 :: "r"(raddr), "l"(v), "r"(rbar) : "memory");
}

// ---- packed f32x2 helpers ----
__device__ __forceinline__ unsigned long long splat2(float a) {
    unsigned long long r; unsigned u = __float_as_uint(a);
    asm("mov.b64 %0, {%1, %1};" : "=l"(r) : "r"(u));
    return r;
}
__device__ __forceinline__ void fma2(unsigned long long& d, unsigned long long a, unsigned long long b) {
    asm("fma.rn.f32x2 %0, %1, %2, %0;" : "+l"(d) : "l"(a), "l"(b));
}
__device__ __forceinline__ unsigned long long add2(unsigned long long a, unsigned long long b) {
    unsigned long long d;
    asm("add.rn.f32x2 %0, %1, %2;" : "=l"(d) : "l"(a), "l"(b));
    return d;
}
__device__ __forceinline__ unsigned long long mul2(unsigned long long a, unsigned long long b) {
    unsigned long long d;
    asm("mul.rn.f32x2 %0, %1, %2;" : "=l"(d) : "l"(a), "l"(b));
    return d;
}

__global__ void __launch_bounds__(NT, 1) __cluster_dims__(Pp, 1, 1)
dirconv_kernel(const float* __restrict__ x, const float* __restrict__ Wg,
               float* __restrict__ out)
{
    float* Ws = sm;
    const unsigned smu = (unsigned)__cvta_generic_to_shared(sm);

    const int tid  = threadIdx.x;
    const int lane = tid & 31;
    const int warp = tid >> 5;
    const int ob   = warp * 8;            // warp's local out-ch base (conv)
    unsigned rank;
    asm("mov.u32 %0, %%cluster_ctarank;" : "=r"(rank));
    const int g     = (int)(rank >> 1);
    const int cg    = (int)(rank & 1u);
    const int cbase = cg * 32;
    const int w0    = g * WC;
    const int b     = blockIdx.x / Pp;
    const int hasL  = (g > 0), hasR = (g < 7);

    const float* xb = x + (size_t)b * Cc * HW;
    float* stk      = g_stack + (size_t)b * Cc * HW;
    float* outb     = out + (size_t)b * Cc * HW;

    const unsigned pb_partner = mapa_rank(smu, rank ^ 1u);
    const unsigned basr = rank & ~1u;
    const unsigned pbL0 = mapa_rank(smu, hasL ? basr - 2u : 0u);
    const unsigned pbL1 = mapa_rank(smu, hasL ? basr - 1u : 0u);
    const unsigned pbR0 = mapa_rank(smu, hasR ? basr + 2u : 0u);
    const unsigned pbR1 = mapa_rank(smu, hasR ? basr + 3u : 0u);

    // expected bytes/step: partner y 4096 + mail 15*256 + halo 256 per existing side
    const unsigned EXPB = 4096u + 3840u + 256u * (unsigned)hasL + 256u * (unsigned)hasR;

    if (tid == 0) { mbar_init(smu + BAR_B(0), 1u); mbar_init(smu + BAR_B(1), 1u); }

    // stage weights: Ws[i*96 + tap*32 + ol] = W[cbase+ol][i][1][tap] (bias cancels in IN)
    for (int idx = tid; idx < 6144; idx += NT) {
        int i   = idx / 96;
        int rem = idx - i * 96;
        int tap = rem >> 5;
        int ol  = rem & 31;
        Ws[idx] = Wg[(size_t)(cbase + ol) * 576 + i * 9 + 3 + tap];
    }

    // build f[0] = x[0] full 64ch x 34col tile into fb[1] (step1 conv input);
    // also write stack row 0 for owned block
    for (int idx = tid; idx < 2176; idx += NT) {
        int ch = idx / 34;
        int c  = idx - ch * 34;
        int gcol = w0 - 1 + c;
        float v = (gcol >= 0 && gcol < Ww) ? xb[(size_t)ch * HW + gcol] : 0.f;
        sm[FB_F(1) + ch * FSTR + c] = v;
        if ((ch >> 5) == cg && c >= 1 && c <= 32)
            stk[(size_t)ch * HW + gcol] = v;
    }

    csync();   // bars initialized + everyone resident

    // epilogue partition: thread -> (channel, col-half)
    const int ch_e = tid >> 1;          // global channel 0..63
    const int s_e  = tid & 1;           // 0: cols 0..16, 1: cols 17..33
    const int c0   = s_e * 17;
    const int ownE = ((ch_e >> 5) == cg);
    const int cgE  = ch_e >> 5;
    const int chl  = ch_e & 31;

    int ph[2] = {0, 0};

    for (int t = 1; t <= 510; ++t) {
        const int fwd = (t <= 255);
        const int row = fwd ? t : 510 - t;
        const float* __restrict__ src = fwd ? xb : stk;
        float* __restrict__ dst = fwd ? stk : outb;
        const int pbuf = t & 1;
        const float* fbR = sm + FB_F(pbuf);          // fn of row t-1 (conv input)
        float* fbW       = sm + FB_F(pbuf ^ 1);      // fn of row t (next conv input)
        const unsigned ybB  = (unsigned)(YB_F(pbuf) * 4);
        const unsigned mlB  = (unsigned)(ML_F(pbuf) * 4);
        const unsigned barB = (unsigned)BAR_B(pbuf);

        // announce expected bytes for THIS step's traffic, then make it visible
        // before any of our own pushes (and order epilogue(t-1) vs conv reads)
        if (tid == 0) mbar_expect(smu + barB, EXPB);
        __syncthreads();

        // backward-scan init: out[255] = f[255] (tile already local in fbR)
        if (t == 256 && ownE) {
#pragma unroll
            for (int j = 1; j <= 16; j++) {
                int c = c0 + ((s_e == 0) ? j : (j + 16 - 16));  // cols 1..16 / 17..32
                int cc = s_e ? (16 + j) : j;
                outb[(size_t)ch_e * HW + (size_t)255 * Ww + (w0 - 1 + cc)] =
                    fbR[ch_e * FSTR + cc];
                (void)c;
            }
        }

        // prefetch residual values for epilogue (17 per thread, edge-masked)
        float xr[17];
#pragma unroll
        for (int j = 0; j < 17; j++) {
            int gcol = w0 - 1 + c0 + j;
            xr[j] = (gcol >= 0 && gcol < Ww)
                  ? src[(size_t)ch_e * HW + (size_t)row * Ww + gcol] : 0.f;
        }

        // conv: lane = col, thread owns 8 out channels as 4 f32x2 pairs
        unsigned long long acc[4] = {0ull, 0ull, 0ull, 0ull};
#pragma unroll 8
        for (int i = 0; i < Cc; i++) {
            float a0 = fbR[i * FSTR + lane];
            float a1 = fbR[i * FSTR + lane + 1];
            float a2 = fbR[i * FSTR + lane + 2];
            unsigned long long s0 = splat2(a0), s1 = splat2(a1), s2 = splat2(a2);
            const ulonglong2* wp = (const ulonglong2*)(Ws + i * 96 + ob);
            ulonglong2 wa = wp[0],  wb = wp[1];
            ulonglong2 wc = wp[8],  wd = wp[9];
            ulonglong2 we = wp[16], wf2 = wp[17];
            fma2(acc[0], s0, wa.x); fma2(acc[1], s0, wa.y);
            fma2(acc[2], s0, wb.x); fma2(acc[3], s0, wb.y);
            fma2(acc[0], s1, wc.x); fma2(acc[1], s1, wc.y);
            fma2(acc[2], s1, wd.x); fma2(acc[3], s1, wd.y);
            fma2(acc[0], s2, we.x); fma2(acc[1], s2, we.y);
            fma2(acc[2], s2, wf2.x); fma2(acc[3], s2, wf2.y);
        }

        // publish y immediately (flight overlaps the reduction below)
        // yb layout: [col 0..33][ch 0..63]; my cols sit at indices 1+lane
#pragma unroll
        for (int j = 0; j < 4; j++) {
            unsigned off = ybB + (unsigned)((1 + lane) * 64 + cbase + ob + 2 * j) * 4u;
            *(unsigned long long*)((char*)sm + off) = acc[j];          // local copy
            st_async_b64(pb_partner + off, acc[j], pb_partner + barB); // partner
        }
        if (lane == 0 && hasL) {     // my col0 -> left pair's col index 33
#pragma unroll
            for (int j = 0; j < 4; j++) {
                unsigned off = ybB + (unsigned)(33 * 64 + cbase + ob + 2 * j) * 4u;
                st_async_b64(pbL0 + off, acc[j], pbL0 + barB);
                st_async_b64(pbL1 + off, acc[j], pbL1 + barB);
            }
        }
        if (lane == 31 && hasR) {    // my col31 -> right pair's col index 0
#pragma unroll
            for (int j = 0; j < 4; j++) {
                unsigned off = ybB + (unsigned)(0 * 64 + cbase + ob + 2 * j) * 4u;
                st_async_b64(pbR0 + off, acc[j], pbR0 + barB);
                st_async_b64(pbR1 + off, acc[j], pbR1 + barB);
            }
        }

        // butterfly reduce over 32 cols (packed sums / sumsq)
        unsigned long long s[4], q[4];
#pragma unroll
        for (int j = 0; j < 4; j++) { s[j] = acc[j]; q[j] = mul2(acc[j], acc[j]); }
#pragma unroll
        for (int off = 16; off >= 1; off >>= 1) {
#pragma unroll
            for (int j = 0; j < 4; j++) {
                s[j] = add2(s[j], __shfl_xor_sync(0xffffffffu, s[j], off));
                q[j] = add2(q[j], __shfl_xor_sync(0xffffffffu, q[j], off));
            }
        }

        // mail: all-to-all partials. lanes 8..15 carry one b64 each.
        if (lane >= 8 && lane < 16) {
            int e   = lane - 8;
            int j   = e & 3;
            int isq = e >> 2;
            unsigned long long val = isq ? q[j] : s[j];
            unsigned moff = mlB + (unsigned)((int)rank * 64 + isq * 32 + ob + 2 * j) * 4u;
            *(unsigned long long*)((char*)sm + moff) = val;   // local slot
#pragma unroll
            for (int p = 0; p < 16; p++) {
                if (p == (int)rank) continue;
                unsigned pb = mapa_rank(smu, (unsigned)p);
                st_async_b64(pb + moff, val, pb + barB);
            }
        }

        __syncthreads();             // local yb/mail stores visible CTA-wide
        mbar_wait(smu + barB, ph[pbuf]);
        ph[pbuf] ^= 1;

        // per-thread stats for its epilogue channel
        const float* ml = sm + ML_F(pbuf);
        float sv = 0.f, qv = 0.f;
#pragma unroll
        for (int g2 = 0; g2 < 8; g2++) {
            int r2 = 2 * g2 + cgE;
            sv += ml[r2 * 64 + chl];
            qv += ml[r2 * 64 + 32 + chl];
        }
        float mean = sv * (1.f / 256.f);
        float var  = qv * (1.f / 256.f) - mean * mean;
        float rstd = rsqrtf(var + 1e-5f);

        // replicated epilogue: fn for (ch_e, cols c0..c0+16); own block also to dst
        const float* yb = sm + YB_F(pbuf);
#pragma unroll
        for (int j = 0; j < 17; j++) {
            int c = c0 + j;
            int pad = (g == 0 && c == 0) || (g == 7 && c == 33);
            float y = yb[c * 64 + ch_e];
            float v = (y - mean) * rstd;
            v = v > 0.f ? v : expm1f(v);
            float fn = pad ? 0.f : (v + xr[j]);
            fbW[ch_e * FSTR + c] = fn;
            if (ownE && c >= 1 && c <= 32)
                dst[(size_t)ch_e * HW + (size_t)row * Ww + (w0 - 1 + c)] = fn;
        }
    }

    csync();   // defensive: no CTA exits while peers might still address its smem
}

extern "C" void kernel_launch(void* const* d_in, const int* in_sizes, int n_in,
                              void* d_out, int out_size)
{
    (void)in_sizes; (void)n_in; (void)out_size;
    const float* x  = (const float*)d_in[0];
    const float* Wg = (const float*)d_in[1];
    // d_in[2] (bias) cancels through InstanceNorm — skipped.
    float* out = (float*)d_out;

    cudaStreamCaptureStatus cs = cudaStreamCaptureStatusNone;
    cudaStreamIsCapturing(0, &cs);
    if (cs == cudaStreamCaptureStatusNone) {
        cudaFuncSetAttribute(dirconv_kernel,
                             cudaFuncAttributeNonPortableClusterSizeAllowed, 1);
        cudaFuncSetAttribute(dirconv_kernel,
                             cudaFuncAttributeMaxDynamicSharedMemorySize, SMEM_BYTES);
    }

    dirconv_kernel<<<Nn * Pp, NT, SMEM_BYTES>>>(x, Wg, out);
}

// round 6
// speedup vs baseline: 1.0581x; 1.0581x over previous
#include <cuda_runtime.h>

#define Nn 8
#define Cc 64
#define Hh 256
#define Ww 256
#define Pp 16          // cluster: 8 col-groups x 2 ch-groups
#define WC 32
#define FSTR 34
#define NT 128
#define HW (Hh*Ww)

// float-index offsets in smem
#define WS_F    0                       // weights: 6144 floats
#define FB_F(b) (6144 + (b)*2176)       // fn tile [64 ch][34]
#define YB_F(b) (10496 + (b)*2176)      // y  tile [64 ch][34]
#define ML_F(b) (14848 + (b)*1024)      // mail    [16 rank][64]
#define YB_B(b) ((10496 + (b)*2176)*4)  // byte offsets for remote stores
#define ML_B(b) ((14848 + (b)*1024)*4)
#define SMEM_BYTES (16896*4)

__device__ float g_stack[(size_t)Nn * Cc * Hh * Ww];

extern __shared__ float sm[];

__device__ __forceinline__ void csync() {
    asm volatile("barrier.cluster.arrive.aligned;" ::: "memory");
    asm volatile("barrier.cluster.wait.aligned;" ::: "memory");
}
__device__ __forceinline__ unsigned mapa_rank(unsigned laddr, unsigned rank) {
    unsigned ra;
    asm("mapa.shared::cluster.u32 %0, %1, %2;" : "=r"(ra) : "r"(laddr), "r"(rank));
    return ra;
}
__device__ __forceinline__ void st_cl_f32(unsigned a, float v) {
    asm volatile("st.shared::cluster.f32 [%0], %1;" :: "r"(a), "f"(v) : "memory");
}
__device__ __forceinline__ void st_cl_b64(unsigned a, unsigned long long v) {
    asm volatile("st.shared::cluster.b64 [%0], %1;" :: "r"(a), "l"(v) : "memory");
}

// ---- packed f32x2 helpers ----
__device__ __forceinline__ unsigned long long splat2(float a) {
    unsigned long long r; unsigned u = __float_as_uint(a);
    asm("mov.b64 %0, {%1, %1};" : "=l"(r) : "r"(u));
    return r;
}
__device__ __forceinline__ void fma2(unsigned long long& d, unsigned long long a, unsigned long long b) {
    asm("fma.rn.f32x2 %0, %1, %2, %0;" : "+l"(d) : "l"(a), "l"(b));
}
__device__ __forceinline__ unsigned long long add2(unsigned long long a, unsigned long long b) {
    unsigned long long d;
    asm("add.rn.f32x2 %0, %1, %2;" : "=l"(d) : "l"(a), "l"(b));
    return d;
}
__device__ __forceinline__ unsigned long long mul2(unsigned long long a, unsigned long long b) {
    unsigned long long d;
    asm("mul.rn.f32x2 %0, %1, %2;" : "=l"(d) : "l"(a), "l"(b));
    return d;
}
__device__ __forceinline__ void unpack2(unsigned long long v, float& lo, float& hi) {
    unsigned ul, uh;
    asm("mov.b64 {%0, %1}, %2;" : "=r"(ul), "=r"(uh) : "l"(v));
    lo = __uint_as_float(ul); hi = __uint_as_float(uh);
}

__global__ void __launch_bounds__(NT, 1) __cluster_dims__(Pp, 1, 1)
dirconv_kernel(const float* __restrict__ x, const float* __restrict__ Wg,
               float* __restrict__ out)
{
    float* Ws = sm;
    const unsigned smu = (unsigned)__cvta_generic_to_shared(sm);

    const int tid  = threadIdx.x;
    const int lane = tid & 31;
    const int warp = tid >> 5;
    const int ob   = warp * 8;            // warp's local out-ch base (conv)
    unsigned rank;
    asm("mov.u32 %0, %%cluster_ctarank;" : "=r"(rank));
    const int g     = (int)(rank >> 1);
    const int cg    = (int)(rank & 1u);
    const int cbase = cg * 32;
    const int w0    = g * WC;
    const int b     = blockIdx.x / Pp;
    const int hasL  = (g > 0), hasR = (g < 7);

    const float* xb = x + (size_t)b * Cc * HW;
    float* stk      = g_stack + (size_t)b * Cc * HW;
    float* outb     = out + (size_t)b * Cc * HW;

    const unsigned pb_partner = mapa_rank(smu, rank ^ 1u);
    const unsigned basr = rank & ~1u;
    const unsigned pbL0 = mapa_rank(smu, hasL ? basr - 2u : 0u);
    const unsigned pbL1 = mapa_rank(smu, hasL ? basr - 1u : 0u);
    const unsigned pbR0 = mapa_rank(smu, hasR ? basr + 2u : 0u);
    const unsigned pbR1 = mapa_rank(smu, hasR ? basr + 3u : 0u);
    unsigned pbAll[16];
#pragma unroll
    for (int p = 0; p < 16; p++) pbAll[p] = mapa_rank(smu, (unsigned)p);

    // stage weights: Ws[i*96 + tap*32 + ol] = W[cbase+ol][i][1][tap] (bias cancels in IN)
    for (int idx = tid; idx < 6144; idx += NT) {
        int i   = idx / 96;
        int rem = idx - i * 96;
        int tap = rem >> 5;
        int ol  = rem & 31;
        Ws[idx] = Wg[(size_t)(cbase + ol) * 576 + i * 9 + 3 + tap];
    }

    // f[0] = x[0]: full 64ch x 34col tile into fb[0] (conv input of step 1);
    // own 32ch x 32col block straight to stack row 0
    for (int idx = tid; idx < 2176; idx += NT) {
        int ch = idx / 34;
        int c  = idx - ch * 34;
        int gcol = w0 - 1 + c;
        float v = (gcol >= 0 && gcol < Ww) ? xb[(size_t)ch * HW + gcol] : 0.f;
        sm[FB_F(0) + ch * FSTR + c] = v;
        if ((ch >> 5) == cg && c >= 1 && c <= 32)
            stk[(size_t)ch * HW + gcol] = v;
    }

    csync();   // everyone resident + staged

    // epilogue partition: thread -> (channel, col-half)
    const int ch_e = tid >> 1;
    const int s_e  = tid & 1;
    const int c0   = s_e * 17;
    const int cgE  = ch_e >> 5;
    const int chl  = ch_e & 31;
    // writeback partition: thread -> (own channel, 8 cols)
    const int ch_a = cbase + (tid >> 2);
    const int coff = (tid & 3) * 8;

    for (int t = 1; t <= 510; ++t) {
        const int fwd = (t <= 255);
        const int row = fwd ? t : 510 - t;
        const float* __restrict__ src = fwd ? xb : stk;
        const int pbuf = t & 1;
        const float* fbR = sm + FB_F(pbuf ^ 1);   // fn(row t-1), built locally by F(t-1)
        float* fbW       = sm + FB_F(pbuf);
        float* ybL       = sm + YB_F(pbuf);
        const unsigned ybB = (unsigned)YB_B(pbuf);
        const unsigned mlB = (unsigned)ML_B(pbuf);

        __syncthreads();   // F(t-1) local writes visible to all threads

        // A: deferred GMEM writeback of row t-1 (own block, read from fbR).
        // Sits right AFTER the previous csync -> its stores drain long before
        // this step's arrive, keeping the release fence empty.
        if (t >= 2) {
            const int pfwd = (t - 1) <= 255;
            const int prow = pfwd ? (t - 1) : (511 - t);
            float* __restrict__ pdst = pfwd ? stk : outb;
            size_t base = (size_t)ch_a * HW + (size_t)prow * Ww + w0 + coff;
            const float* fr = fbR + ch_a * FSTR + 1 + coff;
#pragma unroll
            for (int j = 0; j < 8; j++) pdst[base + j] = fr[j];
        }
        // backward-scan init: out[255] = f[255] (tile local in fbR at t=256)
        if (t == 256) {
            size_t base = (size_t)ch_a * HW + (size_t)255 * Ww + w0 + coff;
            const float* fr = fbR + ch_a * FSTR + 1 + coff;
#pragma unroll
            for (int j = 0; j < 8; j++) outb[base + j] = fr[j];
        }

        // prefetch residuals for the replicated epilogue (17/thread, edge-masked)
        float xr[17];
#pragma unroll
        for (int j = 0; j < 17; j++) {
            int gcol = w0 - 1 + c0 + j;
            xr[j] = (gcol >= 0 && gcol < Ww)
                  ? src[(size_t)ch_e * HW + (size_t)row * Ww + gcol] : 0.f;
        }

        // B: conv — lane = col, thread owns 8 out channels as 4 f32x2 pairs
        unsigned long long acc[4] = {0ull, 0ull, 0ull, 0ull};
#pragma unroll 8
        for (int i = 0; i < Cc; i++) {
            float a0 = fbR[i * FSTR + lane];
            float a1 = fbR[i * FSTR + lane + 1];
            float a2 = fbR[i * FSTR + lane + 2];
            unsigned long long s0 = splat2(a0), s1 = splat2(a1), s2 = splat2(a2);
            const ulonglong2* wp = (const ulonglong2*)(Ws + i * 96 + ob);
            ulonglong2 wa = wp[0],  wb = wp[1];
            ulonglong2 wc = wp[8],  wd = wp[9];
            ulonglong2 we = wp[16], wf2 = wp[17];
            fma2(acc[0], s0, wa.x); fma2(acc[1], s0, wa.y);
            fma2(acc[2], s0, wb.x); fma2(acc[3], s0, wb.y);
            fma2(acc[0], s1, wc.x); fma2(acc[1], s1, wc.y);
            fma2(acc[2], s1, wd.x); fma2(acc[3], s1, wd.y);
            fma2(acc[0], s2, we.x); fma2(acc[1], s2, we.y);
            fma2(acc[2], s2, wf2.x); fma2(acc[3], s2, wf2.y);
        }

        // D: publish y immediately (flight overlaps the reduction below)
        float av[8];
#pragma unroll
        for (int j = 0; j < 4; j++) unpack2(acc[j], av[2 * j], av[2 * j + 1]);
#pragma unroll
        for (int k = 0; k < 8; k++) {
            int chg = cbase + ob + k;
            unsigned off = ybB + (unsigned)(chg * FSTR + 1 + lane) * 4u;
            ybL[chg * FSTR + 1 + lane] = av[k];        // local copy
            st_cl_f32(pb_partner + off, av[k]);        // partner ch-block
        }
        if (lane == 0 && hasL) {
#pragma unroll
            for (int k = 0; k < 8; k++) {
                unsigned ho = ybB + (unsigned)((cbase + ob + k) * FSTR + 33) * 4u;
                st_cl_f32(pbL0 + ho, av[k]); st_cl_f32(pbL1 + ho, av[k]);
            }
        }
        if (lane == 31 && hasR) {
#pragma unroll
            for (int k = 0; k < 8; k++) {
                unsigned ho = ybB + (unsigned)((cbase + ob + k) * FSTR + 0) * 4u;
                st_cl_f32(pbR0 + ho, av[k]); st_cl_f32(pbR1 + ho, av[k]);
            }
        }

        // C: butterfly reduce over 32 cols (packed sums / sumsq)
        unsigned long long s[4], q[4];
#pragma unroll
        for (int j = 0; j < 4; j++) { s[j] = acc[j]; q[j] = mul2(acc[j], acc[j]); }
#pragma unroll
        for (int off = 16; off >= 1; off >>= 1) {
#pragma unroll
            for (int j = 0; j < 4; j++) {
                s[j] = add2(s[j], __shfl_xor_sync(0xffffffffu, s[j], off));
                q[j] = add2(q[j], __shfl_xor_sync(0xffffffffu, q[j], off));
            }
        }
        // mail: push this warp's 8-channel partials to all 16 ranks
        if (lane < 8) {
            int j   = lane & 3;
            int isq = lane >> 2;
            unsigned long long val = isq ? q[j] : s[j];
            unsigned moff = mlB + (unsigned)((int)rank * 64 + isq * 32 + ob + 2 * j) * 4u;
            *(unsigned long long*)((char*)sm + moff) = val;   // local slot
#pragma unroll
            for (int p = 0; p < 16; p++)
                if (p != (int)rank) st_cl_b64(pbAll[p] + moff, val);
        }

        // E: the ONE cluster rendezvous per step
        csync();

        // F: stats (local mail) + replicated epilogue -> fbW (local only)
        const float* ml = sm + ML_F(pbuf);
        float sv = 0.f, qv = 0.f;
#pragma unroll
        for (int g2 = 0; g2 < 8; g2++) {
            int r2 = 2 * g2 + cgE;
            sv += ml[r2 * 64 + chl];
            qv += ml[r2 * 64 + 32 + chl];
        }
        float mean = sv * (1.f / 256.f);
        float var  = qv * (1.f / 256.f) - mean * mean;
        float rstd = rsqrtf(var + 1e-5f);

        const float* yb = sm + YB_F(pbuf);
#pragma unroll
        for (int j = 0; j < 17; j++) {
            int c = c0 + j;
            int pad = (g == 0 && c == 0) || (g == 7 && c == 33);
            float y = yb[ch_e * FSTR + c];
            float v = (y - mean) * rstd;
            v = v > 0.f ? v : expm1f(v);
            float fn = pad ? 0.f : (v + xr[j]);
            fbW[ch_e * FSTR + c] = fn;
        }
    }

    // flush: row 0 (computed by step 510 into fb[0])
    __syncthreads();
    {
        const float* fbR = sm + FB_F(0);
        size_t base = (size_t)ch_a * HW + (size_t)0 * Ww + w0 + coff;
        const float* fr = fbR + ch_a * FSTR + 1 + coff;
#pragma unroll
        for (int j = 0; j < 8; j++) outb[base + j] = fr[j];
    }
}

extern "C" void kernel_launch(void* const* d_in, const int* in_sizes, int n_in,
                              void* d_out, int out_size)
{
    (void)in_sizes; (void)n_in; (void)out_size;
    const float* x  = (const float*)d_in[0];
    const float* Wg = (const float*)d_in[1];
    // d_in[2] (bias) cancels through InstanceNorm — skipped.
    float* out = (float*)d_out;

    cudaStreamCaptureStatus cs = cudaStreamCaptureStatusNone;
    cudaStreamIsCapturing(0, &cs);
    if (cs == cudaStreamCaptureStatusNone) {
        cudaFuncSetAttribute(dirconv_kernel,
                             cudaFuncAttributeNonPortableClusterSizeAllowed, 1);
        cudaFuncSetAttribute(dirconv_kernel,
                             cudaFuncAttributeMaxDynamicSharedMemorySize, SMEM_BYTES);
    }

    dirconv_kernel<<<Nn * Pp, NT, SMEM_BYTES>>>(x, Wg, out);
}

// round 7
// speedup vs baseline: 1.4219x; 1.3438x over previous
#include <cuda_runtime.h>

#define Nn 8
#define Cc 64
#define Hh 256
#define Ww 256
#define Pp 16          // cluster: 8 col-groups x 2 ch-groups
#define WC 32
#define FSTR 34
#define NT 256         // 8 warps: warp = 4 out-ch x 32 cols
#define HW (Hh*Ww)

// float-index smem offsets
#define WS_F    0                      // weights 6144
#define FB_F(b) (6144 + (b)*2176)      // fn tiles [64 ch][34], double buffered
#define ML_F    10496                  // mail [16 rank][64]
#define MR_F    11520                  // mean[32] | rstd[32] (own cg channels)
#define SMEM_BYTES (11584*4)
// byte offsets for remote stores
#define FB_B(b) ((6144 + (b)*2176)*4)
#define ML_B    (10496*4)

__device__ float g_stack[(size_t)Nn * Cc * Hh * Ww];

extern __shared__ float sm[];

__device__ __forceinline__ void csync() {
    asm volatile("barrier.cluster.arrive.aligned;" ::: "memory");
    asm volatile("barrier.cluster.wait.aligned;" ::: "memory");
}
__device__ __forceinline__ unsigned mapa_rank(unsigned laddr, unsigned rank) {
    unsigned ra;
    asm("mapa.shared::cluster.u32 %0, %1, %2;" : "=r"(ra) : "r"(laddr), "r"(rank));
    return ra;
}
__device__ __forceinline__ void st_cl_f32(unsigned a, float v) {
    asm volatile("st.shared::cluster.f32 [%0], %1;" :: "r"(a), "f"(v) : "memory");
}
__device__ __forceinline__ void st_cl_b64(unsigned a, unsigned long long v) {
    asm volatile("st.shared::cluster.b64 [%0], %1;" :: "r"(a), "l"(v) : "memory");
}

// ---- packed f32x2 helpers ----
__device__ __forceinline__ unsigned long long splat2(float a) {
    unsigned long long r; unsigned u = __float_as_uint(a);
    asm("mov.b64 %0, {%1, %1};" : "=l"(r) : "r"(u));
    return r;
}
__device__ __forceinline__ void fma2(unsigned long long& d, unsigned long long a, unsigned long long b) {
    asm("fma.rn.f32x2 %0, %1, %2, %0;" : "+l"(d) : "l"(a), "l"(b));
}
__device__ __forceinline__ unsigned long long add2(unsigned long long a, unsigned long long b) {
    unsigned long long d;
    asm("add.rn.f32x2 %0, %1, %2;" : "=l"(d) : "l"(a), "l"(b));
    return d;
}
__device__ __forceinline__ unsigned long long mul2(unsigned long long a, unsigned long long b) {
    unsigned long long d;
    asm("mul.rn.f32x2 %0, %1, %2;" : "=l"(d) : "l"(a), "l"(b));
    return d;
}
__device__ __forceinline__ void unpack2(unsigned long long v, float& lo, float& hi) {
    unsigned ul, uh;
    asm("mov.b64 {%0, %1}, %2;" : "=r"(ul), "=r"(uh) : "l"(v));
    lo = __uint_as_float(ul); hi = __uint_as_float(uh);
}

__global__ void __launch_bounds__(NT, 1) __cluster_dims__(Pp, 1, 1)
dirconv_kernel(const float* __restrict__ x, const float* __restrict__ Wg,
               float* __restrict__ out)
{
    float* Ws = sm;
    const unsigned smu = (unsigned)__cvta_generic_to_shared(sm);

    const int tid  = threadIdx.x;
    const int lane = tid & 31;
    const int warp = tid >> 5;
    const int ob   = warp * 4;            // warp's local out-ch base (conv/epilogue)
    unsigned rank;
    asm("mov.u32 %0, %%cluster_ctarank;" : "=r"(rank));
    const int g     = (int)(rank >> 1);
    const int cg    = (int)(rank & 1u);
    const int cbase = cg * 32;
    const int w0    = g * WC;
    const int b     = blockIdx.x / Pp;
    const int hasL  = (g > 0), hasR = (g < 7);

    const float* xb = x + (size_t)b * Cc * HW;
    float* stk      = g_stack + (size_t)b * Cc * HW;
    float* outb     = out + (size_t)b * Cc * HW;

    const unsigned pb_partner = mapa_rank(smu, rank ^ 1u);
    const unsigned basr = rank & ~1u;
    const unsigned pbL0 = mapa_rank(smu, hasL ? basr - 2u : 0u);
    const unsigned pbL1 = mapa_rank(smu, hasL ? basr - 1u : 0u);
    const unsigned pbR0 = mapa_rank(smu, hasR ? basr + 2u : 0u);
    const unsigned pbR1 = mapa_rank(smu, hasR ? basr + 3u : 0u);
    unsigned pbSame[8];                     // same-cg ranks (mail targets)
#pragma unroll
    for (int gg = 0; gg < 8; gg++)
        pbSame[gg] = mapa_rank(smu, 2u * (unsigned)gg + (unsigned)cg);

    // stage weights: Ws[i*96 + tap*32 + ol] = W[cbase+ol][i][1][tap] (bias cancels in IN)
    for (int idx = tid; idx < 6144; idx += NT) {
        int i   = idx / 96;
        int rem = idx - i * 96;
        int tap = rem >> 5;
        int ol  = rem & 31;
        Ws[idx] = Wg[(size_t)(cbase + ol) * 576 + i * 9 + 3 + tap];
    }

    // f[0] = x[0]: each CTA builds its FULL 64ch x 34col window locally into fb[0]
    // (conv input of step 1); own 32ch x 32col block straight to stack row 0.
    for (int idx = tid; idx < 2176; idx += NT) {
        int ch = idx / 34;
        int c  = idx - ch * 34;
        int gcol = w0 - 1 + c;
        float v = (gcol >= 0 && gcol < Ww) ? xb[(size_t)ch * HW + gcol] : 0.f;
        sm[FB_F(0) + ch * FSTR + c] = v;
        if ((ch >> 5) == cg && c >= 1 && c <= 32)
            stk[(size_t)ch * HW + gcol] = v;
    }
    // zero cluster-edge halo cols in BOTH buffers (never written otherwise)
    if (g == 0 && tid < 64) { sm[FB_F(0) + tid * FSTR] = 0.f; sm[FB_F(1) + tid * FSTR] = 0.f; }
    if (g == 7 && tid < 64) { sm[FB_F(0) + tid * FSTR + 33] = 0.f; sm[FB_F(1) + tid * FSTR + 33] = 0.f; }

    // deferred-writeback partition: thread -> (own channel, 4 cols)
    const int ch_a = cbase + (tid >> 3);
    const int coff = (tid & 7) * 4;

    for (int t = 1; t <= 510; ++t) {
        const int fwd = (t <= 255);
        const int row = fwd ? t : 510 - t;
        const float* __restrict__ src = fwd ? xb : stk;
        const int pbuf = t & 1;
        const float* fbR = sm + FB_F(pbuf ^ 1);   // fn(row t-1): complete after csync#1
        float* fbW       = sm + FB_F(pbuf);
        const unsigned fbWB = (unsigned)FB_B(pbuf);

        // ===== csync #1: fn(t-1) delivered cluster-wide (also CTA-level sync)
        csync();

        // deferred GMEM writeback of row t-1 (own 32ch x 32col block, from smem).
        // Sits right after the barrier -> stores drain during conv, far from
        // the next release fence.
        if (t >= 2) {
            const int pfwd = (t - 1) <= 255;
            const int prow = pfwd ? (t - 1) : (511 - t);
            float* __restrict__ pdst = pfwd ? stk : outb;
            const float* fr = fbR + ch_a * FSTR + 1 + coff;
            float4 v4 = make_float4(fr[0], fr[1], fr[2], fr[3]);
            *(float4*)(pdst + (size_t)ch_a * HW + (size_t)prow * Ww + w0 + coff) = v4;
        }
        if (t == 256) {   // backward init: out[255] = f[255]
            const float* fr = fbR + ch_a * FSTR + 1 + coff;
            float4 v4 = make_float4(fr[0], fr[1], fr[2], fr[3]);
            *(float4*)(outb + (size_t)ch_a * HW + (size_t)255 * Ww + w0 + coff) = v4;
        }

        // prefetch residuals (4 coalesced LDG/thread), hidden under conv
        float xr[4];
        const size_t rb = (size_t)row * Ww + w0 + lane;
#pragma unroll
        for (int k = 0; k < 4; k++)
            xr[k] = src[(size_t)(cbase + ob + k) * HW + rb];

        // conv: lane = col, warp owns 4 out channels as 2 f32x2 pairs
        unsigned long long acc0 = 0ull, acc1 = 0ull;
#pragma unroll 8
        for (int i = 0; i < Cc; i++) {
            float a0 = fbR[i * FSTR + lane];
            float a1 = fbR[i * FSTR + lane + 1];
            float a2 = fbR[i * FSTR + lane + 2];
            unsigned long long s0 = splat2(a0), s1 = splat2(a1), s2 = splat2(a2);
            const float* wp = Ws + i * 96 + ob;
            ulonglong2 t0 = *(const ulonglong2*)(wp);        // tap 0: ch pairs
            ulonglong2 t1 = *(const ulonglong2*)(wp + 32);   // tap 1
            ulonglong2 t2 = *(const ulonglong2*)(wp + 64);   // tap 2
            fma2(acc0, s0, t0.x); fma2(acc1, s0, t0.y);
            fma2(acc0, s1, t1.x); fma2(acc1, s1, t1.y);
            fma2(acc0, s2, t2.x); fma2(acc1, s2, t2.y);
        }

        // butterfly reduce over 32 cols (packed sums / sumsq)
        unsigned long long s0r = acc0, s1r = acc1;
        unsigned long long q0r = mul2(acc0, acc0), q1r = mul2(acc1, acc1);
#pragma unroll
        for (int off = 16; off >= 1; off >>= 1) {
            s0r = add2(s0r, __shfl_xor_sync(0xffffffffu, s0r, off));
            s1r = add2(s1r, __shfl_xor_sync(0xffffffffu, s1r, off));
            q0r = add2(q0r, __shfl_xor_sync(0xffffffffu, q0r, off));
            q1r = add2(q1r, __shfl_xor_sync(0xffffffffu, q1r, off));
        }
        // push-mail: lanes 0..3 push one b64 each to the 8 same-cg ranks
        if (lane < 4) {
            int j   = lane & 1;                       // which acc pair
            int isq = lane >> 1;                      // 0: sum, 1: sumsq
            unsigned long long val = isq ? (j ? q1r : q0r) : (j ? s1r : s0r);
            unsigned moff = (unsigned)ML_B +
                (unsigned)((int)rank * 64 + isq * 32 + ob + 2 * j) * 4u;
            *(unsigned long long*)((char*)sm + moff) = val;   // local slot
#pragma unroll
            for (int p = 0; p < 8; p++) {
                unsigned pb = pbSame[p];
                if (pb != smu) st_cl_b64(pb + moff, val);
            }
        }

        // ===== csync #2: all partials delivered
        csync();

        // stats for own 32 channels (local mail only)
        if (tid < 32) {
            float sv = 0.f, qv = 0.f;
            const float* ml = sm + ML_F;
#pragma unroll
            for (int g2 = 0; g2 < 8; g2++) {
                int r2 = 2 * g2 + cg;
                sv += ml[r2 * 64 + tid];
                qv += ml[r2 * 64 + 32 + tid];
            }
            float mean = sv * (1.f / 256.f);
            float var  = qv * (1.f / 256.f) - mean * mean;
            sm[MR_F + tid]      = mean;
            sm[MR_F + 32 + tid] = rsqrtf(var + 1e-5f);
        }
        __syncthreads();

        // epilogue: normalize + ELU + residual; write fbW local + remote pushes
        float av[4];
        unpack2(acc0, av[0], av[1]);
        unpack2(acc1, av[2], av[3]);
#pragma unroll
        for (int k = 0; k < 4; k++) {
            int chl = ob + k;
            float m = sm[MR_F + chl], r = sm[MR_F + 32 + chl];
            float v = (av[k] - m) * r;
            v = v > 0.f ? v : (__expf(v) - 1.f);
            float fn = v + xr[k];
            int chg = cbase + chl;
            fbW[chg * FSTR + 1 + lane] = fn;
            unsigned off = fbWB + (unsigned)(chg * FSTR + 1 + lane) * 4u;
            st_cl_f32(pb_partner + off, fn);
            if (lane == 0 && hasL) {
                unsigned ho = fbWB + (unsigned)(chg * FSTR + 33) * 4u;
                st_cl_f32(pbL0 + ho, fn); st_cl_f32(pbL1 + ho, fn);
            }
            if (lane == 31 && hasR) {
                unsigned ho = fbWB + (unsigned)(chg * FSTR + 0) * 4u;
                st_cl_f32(pbR0 + ho, fn); st_cl_f32(pbR1 + ho, fn);
            }
        }
    }

    // final flush: row 0 (produced by step 510 into fb[0])
    __syncthreads();
    {
        const float* fr = sm + FB_F(0) + ch_a * FSTR + 1 + coff;
        float4 v4 = make_float4(fr[0], fr[1], fr[2], fr[3]);
        *(float4*)(outb + (size_t)ch_a * HW + w0 + coff) = v4;
    }
    // no CTA exits while peers may still address its smem
    csync();
}

extern "C" void kernel_launch(void* const* d_in, const int* in_sizes, int n_in,
                              void* d_out, int out_size)
{
    (void)in_sizes; (void)n_in; (void)out_size;
    const float* x  = (const float*)d_in[0];
    const float* Wg = (const float*)d_in[1];
    // d_in[2] (bias) cancels through InstanceNorm — skipped.
    float* out = (float*)d_out;

    cudaStreamCaptureStatus cs = cudaStreamCaptureStatusNone;
    cudaStreamIsCapturing(0, &cs);
    if (cs == cudaStreamCaptureStatusNone) {
        cudaFuncSetAttribute(dirconv_kernel,
                             cudaFuncAttributeNonPortableClusterSizeAllowed, 1);
        cudaFuncSetAttribute(dirconv_kernel,
                             cudaFuncAttributeMaxDynamicSharedMemorySize, SMEM_BYTES);
    }

    dirconv_kernel<<<Nn * Pp, NT, SMEM_BYTES>>>(x, Wg, out);
}